// round 7
// baseline (speedup 1.0000x reference)
#include <cuda_runtime.h>

#define TM 64
#define EPS 1e-5f

#define SH_STRIDE 260   // [64][260]  (row step 1040B == 16B mod 128B: LDSM conflict-free)
#define SA1_STRIDE 68   // [64][68]   (row step 272B  == 16B mod 128B)

// ---------------- device scratch ----------------
__device__ __align__(16) float g_phoneP[100 * 256];
__device__ __align__(16) float g_midiP[128 * 256];
// Fragment-permuted weights: [kt][n][8] where slot j = 2*(k&3) + ((k>>2)&1).
// Lane l of a warp loads its exact m16n8k8 B-fragment {b0,b1} as one 8B read:
//   float2 at ((kt*256 + n)*8 + 2*(l&3)),  n = nbase + (l>>2).
__device__ __align__(16) float g_WfdP[8 * 256 * 8];    // K=64  -> 8 k-tiles
__device__ __align__(16) float g_W2P[32 * 256 * 8];    // K=256 -> 32 k-tiles
__device__ __align__(16) float g_bias[256];

__device__ __forceinline__ float f2tf32(float f) {
    unsigned u;
    asm("cvt.rna.tf32.f32 %0, %1;" : "=r"(u) : "f"(f));
    return __uint_as_float(u);
}

__device__ __forceinline__ unsigned smem_u32(const void* p) {
    unsigned a;
    asm("{ .reg .u64 t; cvta.to.shared.u64 t, %1; cvt.u32.u64 %0, t; }"
        : "=r"(a) : "l"(p));
    return a;
}

__device__ __forceinline__ void ldsm_x4(unsigned& r0, unsigned& r1,
                                        unsigned& r2, unsigned& r3,
                                        unsigned addr) {
    asm volatile("ldmatrix.sync.aligned.m8n8.x4.shared.b16 {%0,%1,%2,%3}, [%4];"
                 : "=r"(r0), "=r"(r1), "=r"(r2), "=r"(r3) : "r"(addr));
}

__device__ __forceinline__ void mma_tf32(float* c, const unsigned* a,
                                         const unsigned* b) {
    asm volatile(
        "mma.sync.aligned.m16n8k8.row.col.f32.tf32.tf32.f32 "
        "{%0,%1,%2,%3}, {%4,%5,%6,%7}, {%8,%9}, {%0,%1,%2,%3};"
        : "+f"(c[0]), "+f"(c[1]), "+f"(c[2]), "+f"(c[3])
        : "r"(a[0]), "r"(a[1]), "r"(a[2]), "r"(a[3]), "r"(b[0]), "r"(b[1]));
}

__device__ __forceinline__ int perm8(int k) {
    return 2 * (k & 3) + ((k >> 2) & 1);
}

// ---------------- precompute ----------------
__global__ void precompute_kernel(
    const float* __restrict__ f0_w2, const float* __restrict__ f0_b2,
    const float* __restrict__ phone_table, const float* __restrict__ midi_table,
    const float* __restrict__ dur_w2, const float* __restrict__ dur_b2,
    const float* __restrict__ proj_w1, const float* __restrict__ proj_b1,
    const float* __restrict__ proj_w2) {
    const int r = blockIdx.x;
    const int c = threadIdx.x;
    if (r < 100) {
        float s = 0.f;
        #pragma unroll 4
        for (int k = 0; k < 128; k++)
            s += phone_table[r * 128 + k] * proj_w1[(64 + k) * 256 + c];
        g_phoneP[r * 256 + c] = s;
    } else if (r < 228) {
        const int m = r - 100;
        float s = 0.f;
        #pragma unroll 4
        for (int k = 0; k < 64; k++)
            s += midi_table[m * 64 + k] * proj_w1[(192 + k) * 256 + c];
        g_midiP[m * 256 + c] = s;
    } else if (r < 260) {
        const int kd = r - 228;
        float s = 0.f;
        #pragma unroll 4
        for (int k = 0; k < 64; k++)
            s += f0_w2[kd * 64 + k] * proj_w1[k * 256 + c];
        g_WfdP[((kd >> 3) * 256 + c) * 8 + perm8(kd)] = f2tf32(s);
    } else if (r < 292) {
        const int j = r - 260;
        const int kd = 32 + j;
        float s = 0.f;
        #pragma unroll 4
        for (int k = 0; k < 64; k++)
            s += dur_w2[j * 64 + k] * proj_w1[(256 + k) * 256 + c];
        g_WfdP[((kd >> 3) * 256 + c) * 8 + perm8(kd)] = f2tf32(s);
    } else if (r < 293) {
        float s = proj_b1[c];
        for (int k = 0; k < 64; k++) {
            s += f0_b2[k] * proj_w1[k * 256 + c];
            s += dur_b2[k] * proj_w1[(256 + k) * 256 + c];
        }
        g_bias[c] = s;
    } else {
        const int k = r - 293;
        g_W2P[((k >> 3) * 256 + c) * 8 + perm8(k)] = f2tf32(proj_w2[k * 256 + c]);
    }
}

// ---------------- main fused kernel (2 CTAs/SM, 3 barriers) ----------------
__global__ __launch_bounds__(256, 2)
void cond_enc_mma_kernel(
    const float* __restrict__ f0, const int* __restrict__ phone,
    const float* __restrict__ duration, const int* __restrict__ midi,
    const float* __restrict__ f0_w1, const float* __restrict__ f0_b1,
    const float* __restrict__ dur_w1, const float* __restrict__ dur_b1,
    const float* __restrict__ ln_g, const float* __restrict__ ln_b,
    const float* __restrict__ proj_b2,
    float* __restrict__ out, int npos) {
    extern __shared__ float sm[];
    float* sH = sm;                        // [64][260]
    float* sa1 = sH + 64 * SH_STRIDE;      // [64][68]
    float* sbias = sa1 + 64 * SA1_STRIDE;  // [256]
    float* sg = sbias + 256;
    float* sb = sg + 256;
    float* sb2 = sb + 256;

    const int tid = threadIdx.x;
    const int lane = tid & 31;
    const int w = tid >> 5;        // warp w owns cols [w*32, w*32+32), all 64 rows
    const int n0w = w * 32;
    const int gid = lane >> 2;
    const int q = lane & 3;
    const int base = blockIdx.x * TM;

    // ldmatrix per-lane offsets (A operand)
    const int tA = lane >> 3;
    const int aRow = (lane & 7) + (tA & 1) * 8;
    const int aKof = (tA >> 1) * 4;

    const unsigned u_sa1 = smem_u32(sa1);
    const unsigned u_sH = smem_u32(sH);

    const float2* __restrict__ W1P = (const float2*)g_WfdP;
    const float2* __restrict__ W2P = (const float2*)g_W2P;
    int nIdx[4];
    #pragma unroll
    for (int nt = 0; nt < 4; nt++) nIdx[nt] = n0w + nt * 8 + gid;

    sbias[tid] = g_bias[tid];
    sg[tid] = ln_g[tid];
    sb[tid] = ln_b[tid];
    sb2[tid] = proj_b2[tid];

    // Phase 1: tiny MLPs -> sa1 (tf32)
    for (int idx = tid; idx < TM * 64; idx += 256) {
        const int t = idx >> 6;
        const int u = idx & 63;
        int row = base + t; if (row >= npos) row = npos - 1;
        float v;
        if (u < 32) v = f0[row] * f0_w1[u] + f0_b1[u];
        else        v = duration[row] * dur_w1[u - 32] + dur_b1[u - 32];
        sa1[t * SA1_STRIDE + u] = f2tf32(fmaxf(v, 0.f));
    }
    __syncthreads();   // (1) sa1 ready

    float acc[4][4][4];
    #pragma unroll
    for (int mt = 0; mt < 4; mt++)
        #pragma unroll
        for (int nt = 0; nt < 4; nt++)
            #pragma unroll
            for (int e = 0; e < 4; e++) acc[mt][nt][e] = 0.f;

    // Phase 2: GEMM1 (K=64, 8 k-tiles), B from L2, 2-tile-ahead prefetch
    {
        float2 bq[2][4];
        #pragma unroll
        for (int nt = 0; nt < 4; nt++) {
            bq[0][nt] = W1P[(0 * 256 + nIdx[nt]) * 4 + q];
            bq[1][nt] = W1P[(1 * 256 + nIdx[nt]) * 4 + q];
        }
        #pragma unroll
        for (int kt = 0; kt < 8; kt++) {
            const int cur = kt & 1;
            unsigned a[4][4];
            #pragma unroll
            for (int mt = 0; mt < 4; mt++)
                ldsm_x4(a[mt][0], a[mt][1], a[mt][2], a[mt][3],
                        u_sa1 + (unsigned)((mt * 16 + aRow) * SA1_STRIDE +
                                           kt * 8 + aKof) * 4u);
            #pragma unroll
            for (int mt = 0; mt < 4; mt++)
                #pragma unroll
                for (int nt = 0; nt < 4; nt++)
                    mma_tf32(acc[mt][nt], a[mt], (const unsigned*)&bq[cur][nt]);
            if (kt < 6) {
                #pragma unroll
                for (int nt = 0; nt < 4; nt++)
                    bq[cur][nt] = W1P[((kt + 2) * 256 + nIdx[nt]) * 4 + q];
            }
        }
    }

    // Epilogue1: acc -> sH
    #pragma unroll
    for (int mt = 0; mt < 4; mt++) {
        const int row = mt * 16 + gid;
        #pragma unroll
        for (int nt = 0; nt < 4; nt++) {
            const int col = n0w + nt * 8 + q * 2;
            *(float2*)&sH[row * SH_STRIDE + col] =
                make_float2(acc[mt][nt][0], acc[mt][nt][1]);
            *(float2*)&sH[(row + 8) * SH_STRIDE + col] =
                make_float2(acc[mt][nt][2], acc[mt][nt][3]);
        }
    }
    __syncthreads();   // (2) sH(h) complete

    // Phase 3: bias + phone/midi tables, LayerNorm, ReLU (warp per row).
    // Column map c = lane*8 + h*4 + e (vectorized float4; sums are
    // permutation-invariant and all per-col vectors use the same map).
    #pragma unroll 2
    for (int rr = 0; rr < 8; rr++) {
        const int r = w * 8 + rr;
        int grow = base + r; if (grow >= npos) grow = npos - 1;
        const int p = phone[grow];
        const int m = midi[grow];
        const float4* __restrict__ pp4 = (const float4*)&g_phoneP[p * 256];
        const float4* __restrict__ mp4 = (const float4*)&g_midiP[m * 256];
        const float4* __restrict__ bb4 = (const float4*)sbias;
        float4 v4[2];
        float s = 0.f, ss = 0.f;
        #pragma unroll
        for (int h = 0; h < 2; h++) {
            const int c4 = lane * 2 + h;
            float4 x = *(const float4*)&sH[r * SH_STRIDE + c4 * 4];
            const float4 a = pp4[c4];
            const float4 b = mp4[c4];
            const float4 d = bb4[c4];
            x.x += a.x + b.x + d.x;
            x.y += a.y + b.y + d.y;
            x.z += a.z + b.z + d.z;
            x.w += a.w + b.w + d.w;
            s += x.x + x.y + x.z + x.w;
            ss += x.x * x.x + x.y * x.y + x.z * x.z + x.w * x.w;
            v4[h] = x;
        }
        #pragma unroll
        for (int o = 16; o > 0; o >>= 1) {
            s += __shfl_xor_sync(0xffffffffu, s, o);
            ss += __shfl_xor_sync(0xffffffffu, ss, o);
        }
        const float mu = s * (1.f / 256.f);
        float var = ss * (1.f / 256.f) - mu * mu;
        var = fmaxf(var, 0.f);
        const float rs = rsqrtf(var + EPS);
        #pragma unroll
        for (int h = 0; h < 2; h++) {
            const int c4 = lane * 2 + h;
            const float4 g4 = ((const float4*)sg)[c4];
            const float4 b4 = ((const float4*)sb)[c4];
            float4 x = v4[h];
            x.x = f2tf32(fmaxf((x.x - mu) * rs * g4.x + b4.x, 0.f));
            x.y = f2tf32(fmaxf((x.y - mu) * rs * g4.y + b4.y, 0.f));
            x.z = f2tf32(fmaxf((x.z - mu) * rs * g4.z + b4.z, 0.f));
            x.w = f2tf32(fmaxf((x.w - mu) * rs * g4.w + b4.w, 0.f));
            *(float4*)&sH[r * SH_STRIDE + c4 * 4] = x;
        }
    }
    __syncthreads();   // (3) activations ready

    #pragma unroll
    for (int mt = 0; mt < 4; mt++)
        #pragma unroll
        for (int nt = 0; nt < 4; nt++)
            #pragma unroll
            for (int e = 0; e < 4; e++) acc[mt][nt][e] = 0.f;

    // Phase 4: GEMM2 (K=256, 32 k-tiles), barrier-free, 2-tile-ahead B prefetch
    {
        float2 bq[2][4];
        #pragma unroll
        for (int nt = 0; nt < 4; nt++) {
            bq[0][nt] = W2P[(0 * 256 + nIdx[nt]) * 4 + q];
            bq[1][nt] = W2P[(1 * 256 + nIdx[nt]) * 4 + q];
        }
        #pragma unroll 4
        for (int kt = 0; kt < 32; kt++) {
            const int cur = kt & 1;
            unsigned a[4][4];
            #pragma unroll
            for (int mt = 0; mt < 4; mt++)
                ldsm_x4(a[mt][0], a[mt][1], a[mt][2], a[mt][3],
                        u_sH + (unsigned)((mt * 16 + aRow) * SH_STRIDE +
                                          kt * 8 + aKof) * 4u);
            #pragma unroll
            for (int mt = 0; mt < 4; mt++)
                #pragma unroll
                for (int nt = 0; nt < 4; nt++)
                    mma_tf32(acc[mt][nt], a[mt], (const unsigned*)&bq[cur][nt]);
            if (kt < 30) {
                #pragma unroll
                for (int nt = 0; nt < 4; nt++)
                    bq[cur][nt] = W2P[((kt + 2) * 256 + nIdx[nt]) * 4 + q];
            }
        }
    }

    // Phase 5: write output (+proj_b2)
    #pragma unroll
    for (int mt = 0; mt < 4; mt++) {
        const int row = mt * 16 + gid;
        #pragma unroll
        for (int nt = 0; nt < 4; nt++) {
            const int col = n0w + nt * 8 + q * 2;
            const float b2a = sb2[col];
            const float b2b = sb2[col + 1];
            if (base + row < npos)
                *(float2*)&out[(size_t)(base + row) * 256 + col] =
                    make_float2(acc[mt][nt][0] + b2a, acc[mt][nt][1] + b2b);
            if (base + row + 8 < npos)
                *(float2*)&out[(size_t)(base + row + 8) * 256 + col] =
                    make_float2(acc[mt][nt][2] + b2a, acc[mt][nt][3] + b2b);
        }
    }
}

extern "C" void kernel_launch(void* const* d_in, const int* in_sizes, int n_in,
                              void* d_out, int out_size) {
    const float* f0          = (const float*)d_in[0];
    const int*   phone       = (const int*)  d_in[1];
    const float* duration    = (const float*)d_in[2];
    const int*   midi        = (const int*)  d_in[3];
    const float* f0_w1       = (const float*)d_in[4];
    const float* f0_b1       = (const float*)d_in[5];
    const float* f0_w2       = (const float*)d_in[6];
    const float* f0_b2       = (const float*)d_in[7];
    const float* phone_table = (const float*)d_in[8];
    const float* midi_table  = (const float*)d_in[9];
    const float* dur_w1      = (const float*)d_in[10];
    const float* dur_b1      = (const float*)d_in[11];
    const float* dur_w2      = (const float*)d_in[12];
    const float* dur_b2      = (const float*)d_in[13];
    const float* proj_w1     = (const float*)d_in[14];
    const float* proj_b1     = (const float*)d_in[15];
    const float* ln_g        = (const float*)d_in[16];
    const float* ln_b        = (const float*)d_in[17];
    const float* proj_w2     = (const float*)d_in[18];
    const float* proj_b2     = (const float*)d_in[19];
    float* out = (float*)d_out;
    const int npos = in_sizes[0];

    precompute_kernel<<<549, 256>>>(f0_w2, f0_b2, phone_table, midi_table,
                                    dur_w2, dur_b2, proj_w1, proj_b1, proj_w2);

    const size_t smem_bytes =
        (size_t)(64 * SH_STRIDE + 64 * SA1_STRIDE + 4 * 256) * sizeof(float);
    cudaFuncSetAttribute(cond_enc_mma_kernel,
                         cudaFuncAttributeMaxDynamicSharedMemorySize,
                         (int)smem_bytes);
    const int grid = (npos + TM - 1) / TM;
    cond_enc_mma_kernel<<<grid, 256, smem_bytes>>>(
        f0, phone, duration, midi, f0_w1, f0_b1, dur_w1, dur_b1,
        ln_g, ln_b, proj_b2, out, npos);
}

// round 8
// speedup vs baseline: 1.4832x; 1.4832x over previous
#include <cuda_runtime.h>
#include <cuda_fp16.h>

#define TM 64
#define EPS 1e-5f

#define SA1H 72    // [64][72] halves: row step 144B == 16B mod 128B (LDSM-clean)
#define SA2H 264   // [64][264] halves: row step 528B == 16B mod 128B
#define PS_STRIDE 9

// ---------------- device scratch ----------------
__device__ __align__(16) float g_phoneP[100 * 256];
__device__ __align__(16) float g_midiP[128 * 256];
__device__ __align__(16) float g_bias[256];
// fp16 fragment-packed B: [kt16][n=256][16 halves]; lane q reads halves
// [q*4 .. q*4+3] = k elements {2q, 2q+1, 2q+8, 2q+9} of that 16-k tile (one 8B read).
__device__ __align__(16) __half g_W1H[4 * 256 * 16];    // K=64  -> 4 k-tiles
__device__ __align__(16) __half g_W2H[16 * 256 * 16];   // K=256 -> 16 k-tiles

__host__ __device__ __forceinline__ int slot16(int kk) {
    return ((kk & 7) >> 1) * 4 + ((kk >> 3) & 1) * 2 + (kk & 1);
}

__device__ __forceinline__ unsigned smem_u32(const void* p) {
    unsigned a;
    asm("{ .reg .u64 t; cvta.to.shared.u64 t, %1; cvt.u32.u64 %0, t; }"
        : "=r"(a) : "l"(p));
    return a;
}

__device__ __forceinline__ void ldsm_x4(unsigned& r0, unsigned& r1,
                                        unsigned& r2, unsigned& r3,
                                        unsigned addr) {
    asm volatile("ldmatrix.sync.aligned.m8n8.x4.shared.b16 {%0,%1,%2,%3}, [%4];"
                 : "=r"(r0), "=r"(r1), "=r"(r2), "=r"(r3) : "r"(addr));
}

__device__ __forceinline__ void mma_f16(float* c, const unsigned* a,
                                        const unsigned* b) {
    asm volatile(
        "mma.sync.aligned.m16n8k16.row.col.f32.f16.f16.f32 "
        "{%0,%1,%2,%3}, {%4,%5,%6,%7}, {%8,%9}, {%0,%1,%2,%3};"
        : "+f"(c[0]), "+f"(c[1]), "+f"(c[2]), "+f"(c[3])
        : "r"(a[0]), "r"(a[1]), "r"(a[2]), "r"(a[3]), "r"(b[0]), "r"(b[1]));
}

// ---------------- precompute ----------------
__global__ void precompute_kernel(
    const float* __restrict__ f0_w2, const float* __restrict__ f0_b2,
    const float* __restrict__ phone_table, const float* __restrict__ midi_table,
    const float* __restrict__ dur_w2, const float* __restrict__ dur_b2,
    const float* __restrict__ proj_w1, const float* __restrict__ proj_b1,
    const float* __restrict__ proj_w2) {
    const int r = blockIdx.x;
    const int c = threadIdx.x;
    if (r < 100) {
        float s = 0.f;
        #pragma unroll 4
        for (int k = 0; k < 128; k++)
            s += phone_table[r * 128 + k] * proj_w1[(64 + k) * 256 + c];
        g_phoneP[r * 256 + c] = s;
    } else if (r < 228) {
        const int m = r - 100;
        float s = 0.f;
        #pragma unroll 4
        for (int k = 0; k < 64; k++)
            s += midi_table[m * 64 + k] * proj_w1[(192 + k) * 256 + c];
        g_midiP[m * 256 + c] = s;
    } else if (r < 260) {
        const int kd = r - 228;          // derived-K index 0..31 (f0 part)
        float s = 0.f;
        #pragma unroll 4
        for (int k = 0; k < 64; k++)
            s += f0_w2[kd * 64 + k] * proj_w1[k * 256 + c];
        g_W1H[((kd >> 4) * 256 + c) * 16 + slot16(kd & 15)] = __float2half_rn(s);
    } else if (r < 292) {
        const int j = r - 260;           // dur part -> derived-K 32..63
        const int kd = 32 + j;
        float s = 0.f;
        #pragma unroll 4
        for (int k = 0; k < 64; k++)
            s += dur_w2[j * 64 + k] * proj_w1[(256 + k) * 256 + c];
        g_W1H[((kd >> 4) * 256 + c) * 16 + slot16(kd & 15)] = __float2half_rn(s);
    } else if (r < 293) {
        float s = proj_b1[c];
        for (int k = 0; k < 64; k++) {
            s += f0_b2[k] * proj_w1[k * 256 + c];
            s += dur_b2[k] * proj_w1[(256 + k) * 256 + c];
        }
        g_bias[c] = s;
    } else {
        const int k = r - 293;           // 0..255: proj_w2 input-row k, col c
        g_W2H[((k >> 4) * 256 + c) * 16 + slot16(k & 15)] =
            __float2half_rn(proj_w2[k * 256 + c]);
    }
}

// ---------------- main fused fp16-mma kernel (2 CTAs/SM) ----------------
__global__ __launch_bounds__(256, 2)
void cond_enc_mma_kernel(
    const float* __restrict__ f0, const int* __restrict__ phone,
    const float* __restrict__ duration, const int* __restrict__ midi,
    const float* __restrict__ f0_w1, const float* __restrict__ f0_b1,
    const float* __restrict__ dur_w1, const float* __restrict__ dur_b1,
    const float* __restrict__ ln_g, const float* __restrict__ ln_b,
    const float* __restrict__ proj_b2,
    float* __restrict__ out, int npos) {
    extern __shared__ __align__(16) char smraw[];
    __half* sa1 = (__half*)smraw;                       // [64][72]
    __half* sA2 = sa1 + 64 * SA1H;                      // [64][264]
    float2* sPS = (float2*)(sA2 + 64 * SA2H);           // [64][9] partials
    float2* sMV = sPS + 64 * PS_STRIDE;                 // [64] (mu, rs)
    float* sbias = (float*)(sMV + 64);                  // [256]
    float* sg = sbias + 256;
    float* sb = sg + 256;
    float* sb2 = sb + 256;

    const int tid = threadIdx.x;
    const int lane = tid & 31;
    const int w = tid >> 5;          // warp w owns cols [w*32, w*32+32), all 64 rows
    const int n0w = w * 32;
    const int gid = lane >> 2;
    const int q = lane & 3;
    const int base = blockIdx.x * TM;

    // ldmatrix per-lane A offsets (b16, 16-k tiles)
    const int tA = lane >> 3;
    const int aRow = (lane & 7) + (tA & 1) * 8;
    const int aKof = (tA >> 1) * 8;       // halves

    const unsigned u_sa1 = smem_u32(sa1);
    const unsigned u_sA2 = smem_u32(sA2);

    const uint2* __restrict__ W1H = (const uint2*)g_W1H;
    const uint2* __restrict__ W2H = (const uint2*)g_W2H;
    int nIdx[4];
    #pragma unroll
    for (int nt = 0; nt < 4; nt++) nIdx[nt] = n0w + nt * 8 + gid;

    sbias[tid] = g_bias[tid];
    sg[tid] = ln_g[tid];
    sb[tid] = ln_b[tid];
    sb2[tid] = proj_b2[tid];

    // Phase 1: tiny MLPs -> sa1 (half2 stores)
    for (int idx = tid; idx < TM * 32; idx += 256) {
        const int t = idx >> 5;
        const int u = (idx & 31) * 2;
        int row = base + t; if (row >= npos) row = npos - 1;
        float v0, v1;
        if (u < 32) {
            const float fv = f0[row];
            v0 = fv * f0_w1[u] + f0_b1[u];
            v1 = fv * f0_w1[u + 1] + f0_b1[u + 1];
        } else {
            const float dv = duration[row];
            v0 = dv * dur_w1[u - 32] + dur_b1[u - 32];
            v1 = dv * dur_w1[u - 31] + dur_b1[u - 31];
        }
        *(__half2*)&sa1[t * SA1H + u] =
            __floats2half2_rn(fmaxf(v0, 0.f), fmaxf(v1, 0.f));
    }
    __syncthreads();   // (1) sa1 ready

    float acc[4][4][4];
    #pragma unroll
    for (int mt = 0; mt < 4; mt++)
        #pragma unroll
        for (int nt = 0; nt < 4; nt++)
            #pragma unroll
            for (int e = 0; e < 4; e++) acc[mt][nt][e] = 0.f;

    // Phase 2: GEMM1 (K=64 -> 4 fp16 k-tiles), B direct from L2
    {
        uint2 bq[2][4];
        #pragma unroll
        for (int nt = 0; nt < 4; nt++)
            bq[0][nt] = W1H[(0 * 256 + nIdx[nt]) * 4 + q];
        #pragma unroll
        for (int kt = 0; kt < 4; kt++) {
            const int cur = kt & 1, nxt = cur ^ 1;
            if (kt < 3) {
                #pragma unroll
                for (int nt = 0; nt < 4; nt++)
                    bq[nxt][nt] = W1H[((kt + 1) * 256 + nIdx[nt]) * 4 + q];
            }
            unsigned a[4][4];
            #pragma unroll
            for (int mt = 0; mt < 4; mt++)
                ldsm_x4(a[mt][0], a[mt][1], a[mt][2], a[mt][3],
                        u_sa1 + (unsigned)((mt * 16 + aRow) * SA1H +
                                           kt * 16 + aKof) * 2u);
            #pragma unroll
            for (int mt = 0; mt < 4; mt++)
                #pragma unroll
                for (int nt = 0; nt < 4; nt++)
                    mma_f16(acc[mt][nt], a[mt], (const unsigned*)&bq[cur][nt]);
        }
    }

    // Phase 3a: add bias + phone/midi table contributions in-register,
    // accumulate per-row partial sums for LayerNorm.
    {
        #pragma unroll
        for (int mt = 0; mt < 4; mt++) {
            const int r0 = mt * 16 + gid;
            const int r1 = r0 + 8;
            int g0 = base + r0; if (g0 >= npos) g0 = npos - 1;
            int g1 = base + r1; if (g1 >= npos) g1 = npos - 1;
            const float* __restrict__ pp0 = &g_phoneP[phone[g0] * 256];
            const float* __restrict__ mp0 = &g_midiP[midi[g0] * 256];
            const float* __restrict__ pp1 = &g_phoneP[phone[g1] * 256];
            const float* __restrict__ mp1 = &g_midiP[midi[g1] * 256];
            float s0 = 0.f, ss0 = 0.f, s1 = 0.f, ss1 = 0.f;
            #pragma unroll
            for (int nt = 0; nt < 4; nt++) {
                const int col = n0w + nt * 8 + q * 2;
                const float2 bb = *(const float2*)&sbias[col];
                const float2 a0 = *(const float2*)&pp0[col];
                const float2 b0 = *(const float2*)&mp0[col];
                const float2 a1 = *(const float2*)&pp1[col];
                const float2 b1 = *(const float2*)&mp1[col];
                float x0 = acc[mt][nt][0] + bb.x + a0.x + b0.x;
                float x1 = acc[mt][nt][1] + bb.y + a0.y + b0.y;
                float x2 = acc[mt][nt][2] + bb.x + a1.x + b1.x;
                float x3 = acc[mt][nt][3] + bb.y + a1.y + b1.y;
                acc[mt][nt][0] = x0; acc[mt][nt][1] = x1;
                acc[mt][nt][2] = x2; acc[mt][nt][3] = x3;
                s0 += x0 + x1; ss0 += x0 * x0 + x1 * x1;
                s1 += x2 + x3; ss1 += x2 * x2 + x3 * x3;
            }
            // reduce across the 4 q-lanes of this row group
            #pragma unroll
            for (int o = 1; o < 4; o <<= 1) {
                s0 += __shfl_xor_sync(0xffffffffu, s0, o);
                ss0 += __shfl_xor_sync(0xffffffffu, ss0, o);
                s1 += __shfl_xor_sync(0xffffffffu, s1, o);
                ss1 += __shfl_xor_sync(0xffffffffu, ss1, o);
            }
            if (q == 0) {
                sPS[r0 * PS_STRIDE + w] = make_float2(s0, ss0);
                sPS[r1 * PS_STRIDE + w] = make_float2(s1, ss1);
            }
        }
    }
    __syncthreads();   // (2) partials ready

    // Phase 3b: finalize mu/rs per row (threads 0..63)
    if (tid < 64) {
        float s = 0.f, ss = 0.f;
        #pragma unroll
        for (int j = 0; j < 8; j++) {
            const float2 ps = sPS[tid * PS_STRIDE + j];
            s += ps.x; ss += ps.y;
        }
        const float mu = s * (1.f / 256.f);
        float var = ss * (1.f / 256.f) - mu * mu;
        var = fmaxf(var, 0.f);
        sMV[tid] = make_float2(mu, rsqrtf(var + EPS));
    }
    __syncthreads();   // (3) mu/rs ready

    // Phase 3c: apply LN + ReLU in-register, write half A2 tile
    {
        #pragma unroll
        for (int mt = 0; mt < 4; mt++) {
            const int r0 = mt * 16 + gid;
            const int r1 = r0 + 8;
            const float2 mv0 = sMV[r0];
            const float2 mv1 = sMV[r1];
            #pragma unroll
            for (int nt = 0; nt < 4; nt++) {
                const int col = n0w + nt * 8 + q * 2;
                const float2 gg = *(const float2*)&sg[col];
                const float2 bb = *(const float2*)&sb[col];
                float x0 = fmaxf((acc[mt][nt][0] - mv0.x) * mv0.y * gg.x + bb.x, 0.f);
                float x1 = fmaxf((acc[mt][nt][1] - mv0.x) * mv0.y * gg.y + bb.y, 0.f);
                float x2 = fmaxf((acc[mt][nt][2] - mv1.x) * mv1.y * gg.x + bb.x, 0.f);
                float x3 = fmaxf((acc[mt][nt][3] - mv1.x) * mv1.y * gg.y + bb.y, 0.f);
                *(__half2*)&sA2[r0 * SA2H + col] = __floats2half2_rn(x0, x1);
                *(__half2*)&sA2[r1 * SA2H + col] = __floats2half2_rn(x2, x3);
            }
        }
    }
    __syncthreads();   // (4) A2 ready

    #pragma unroll
    for (int mt = 0; mt < 4; mt++)
        #pragma unroll
        for (int nt = 0; nt < 4; nt++)
            #pragma unroll
            for (int e = 0; e < 4; e++) acc[mt][nt][e] = 0.f;

    // Phase 4: GEMM2 (K=256 -> 16 fp16 k-tiles), barrier-free, B from L2
    {
        uint2 bq[2][4];
        #pragma unroll
        for (int nt = 0; nt < 4; nt++)
            bq[0][nt] = W2H[(0 * 256 + nIdx[nt]) * 4 + q];
        #pragma unroll 4
        for (int kt = 0; kt < 16; kt++) {
            const int cur = kt & 1, nxt = cur ^ 1;
            if (kt < 15) {
                #pragma unroll
                for (int nt = 0; nt < 4; nt++)
                    bq[nxt][nt] = W2H[((kt + 1) * 256 + nIdx[nt]) * 4 + q];
            }
            unsigned a[4][4];
            #pragma unroll
            for (int mt = 0; mt < 4; mt++)
                ldsm_x4(a[mt][0], a[mt][1], a[mt][2], a[mt][3],
                        u_sA2 + (unsigned)((mt * 16 + aRow) * SA2H +
                                           kt * 16 + aKof) * 2u);
            #pragma unroll
            for (int mt = 0; mt < 4; mt++)
                #pragma unroll
                for (int nt = 0; nt < 4; nt++)
                    mma_f16(acc[mt][nt], a[mt], (const unsigned*)&bq[cur][nt]);
        }
    }

    // Phase 5: write output (+proj_b2)
    #pragma unroll
    for (int mt = 0; mt < 4; mt++) {
        const int row = mt * 16 + gid;
        #pragma unroll
        for (int nt = 0; nt < 4; nt++) {
            const int col = n0w + nt * 8 + q * 2;
            const float b2a = sb2[col];
            const float b2b = sb2[col + 1];
            if (base + row < npos)
                *(float2*)&out[(size_t)(base + row) * 256 + col] =
                    make_float2(acc[mt][nt][0] + b2a, acc[mt][nt][1] + b2b);
            if (base + row + 8 < npos)
                *(float2*)&out[(size_t)(base + row + 8) * 256 + col] =
                    make_float2(acc[mt][nt][2] + b2a, acc[mt][nt][3] + b2b);
        }
    }
}

extern "C" void kernel_launch(void* const* d_in, const int* in_sizes, int n_in,
                              void* d_out, int out_size) {
    const float* f0          = (const float*)d_in[0];
    const int*   phone       = (const int*)  d_in[1];
    const float* duration    = (const float*)d_in[2];
    const int*   midi        = (const int*)  d_in[3];
    const float* f0_w1       = (const float*)d_in[4];
    const float* f0_b1       = (const float*)d_in[5];
    const float* f0_w2       = (const float*)d_in[6];
    const float* f0_b2       = (const float*)d_in[7];
    const float* phone_table = (const float*)d_in[8];
    const float* midi_table  = (const float*)d_in[9];
    const float* dur_w1      = (const float*)d_in[10];
    const float* dur_b1      = (const float*)d_in[11];
    const float* dur_w2      = (const float*)d_in[12];
    const float* dur_b2      = (const float*)d_in[13];
    const float* proj_w1     = (const float*)d_in[14];
    const float* proj_b1     = (const float*)d_in[15];
    const float* ln_g        = (const float*)d_in[16];
    const float* ln_b        = (const float*)d_in[17];
    const float* proj_w2     = (const float*)d_in[18];
    const float* proj_b2     = (const float*)d_in[19];
    float* out = (float*)d_out;
    const int npos = in_sizes[0];

    precompute_kernel<<<549, 256>>>(f0_w2, f0_b2, phone_table, midi_table,
                                    dur_w2, dur_b2, proj_w1, proj_b1, proj_w2);

    const size_t smem_bytes =
        (size_t)(64 * SA1H + 64 * SA2H) * sizeof(__half) +
        (size_t)(64 * PS_STRIDE + 64) * sizeof(float2) +
        (size_t)(4 * 256) * sizeof(float) + 64;
    cudaFuncSetAttribute(cond_enc_mma_kernel,
                         cudaFuncAttributeMaxDynamicSharedMemorySize,
                         (int)smem_bytes);
    const int grid = (npos + TM - 1) / TM;
    cond_enc_mma_kernel<<<grid, 256, smem_bytes>>>(
        f0, phone, duration, midi, f0_w1, f0_b1, dur_w1, dur_b1,
        ln_g, ln_b, proj_b2, out, npos);
}

// round 9
// speedup vs baseline: 1.5667x; 1.0563x over previous
#include <cuda_runtime.h>
#include <cuda_fp16.h>

#define TM 64
#define EPS 1e-5f

#define SA1H 72    // [64][72] halves: row step 144B == 16B mod 128B (LDSM-clean)
#define SA2H 264   // [64][264] halves: row step 528B == 16B mod 128B
#define PS_STRIDE 9

// ---------------- device scratch ----------------
__device__ __align__(16) __half g_phonePh[100 * 256];   // fp16 folded phone table
__device__ __align__(16) __half g_midiPh[128 * 256];    // fp16 folded midi table
__device__ __align__(16) float g_bias[256];
// fp16 fragment-packed B: [kt16][n=256][16 halves]; lane q reads halves
// [q*4 .. q*4+3] = k elements {2q, 2q+1, 2q+8, 2q+9} of that 16-k tile (one 8B read).
__device__ __align__(16) __half g_W1H[4 * 256 * 16];    // K=64  -> 4 k-tiles
__device__ __align__(16) __half g_W2H[16 * 256 * 16];   // K=256 -> 16 k-tiles

__host__ __device__ __forceinline__ int slot16(int kk) {
    return ((kk & 7) >> 1) * 4 + ((kk >> 3) & 1) * 2 + (kk & 1);
}

__device__ __forceinline__ unsigned smem_u32(const void* p) {
    unsigned a;
    asm("{ .reg .u64 t; cvta.to.shared.u64 t, %1; cvt.u32.u64 %0, t; }"
        : "=r"(a) : "l"(p));
    return a;
}

__device__ __forceinline__ void ldsm_x4(unsigned& r0, unsigned& r1,
                                        unsigned& r2, unsigned& r3,
                                        unsigned addr) {
    asm volatile("ldmatrix.sync.aligned.m8n8.x4.shared.b16 {%0,%1,%2,%3}, [%4];"
                 : "=r"(r0), "=r"(r1), "=r"(r2), "=r"(r3) : "r"(addr));
}

__device__ __forceinline__ void mma_f16(float* c, const unsigned* a,
                                        const unsigned* b) {
    asm volatile(
        "mma.sync.aligned.m16n8k16.row.col.f32.f16.f16.f32 "
        "{%0,%1,%2,%3}, {%4,%5,%6,%7}, {%8,%9}, {%0,%1,%2,%3};"
        : "+f"(c[0]), "+f"(c[1]), "+f"(c[2]), "+f"(c[3])
        : "r"(a[0]), "r"(a[1]), "r"(a[2]), "r"(a[3]), "r"(b[0]), "r"(b[1]));
}

// ---------------- precompute (4 independent accumulators: short dep chains) ----
__global__ void precompute_kernel(
    const float* __restrict__ f0_w2, const float* __restrict__ f0_b2,
    const float* __restrict__ phone_table, const float* __restrict__ midi_table,
    const float* __restrict__ dur_w2, const float* __restrict__ dur_b2,
    const float* __restrict__ proj_w1, const float* __restrict__ proj_b1,
    const float* __restrict__ proj_w2) {
    const int r = blockIdx.x;
    const int c = threadIdx.x;
    if (r < 100) {
        float s0 = 0.f, s1 = 0.f, s2 = 0.f, s3 = 0.f;
        #pragma unroll 8
        for (int k = 0; k < 128; k += 4) {
            s0 += phone_table[r * 128 + k + 0] * proj_w1[(64 + k + 0) * 256 + c];
            s1 += phone_table[r * 128 + k + 1] * proj_w1[(64 + k + 1) * 256 + c];
            s2 += phone_table[r * 128 + k + 2] * proj_w1[(64 + k + 2) * 256 + c];
            s3 += phone_table[r * 128 + k + 3] * proj_w1[(64 + k + 3) * 256 + c];
        }
        g_phonePh[r * 256 + c] = __float2half_rn((s0 + s1) + (s2 + s3));
    } else if (r < 228) {
        const int m = r - 100;
        float s0 = 0.f, s1 = 0.f, s2 = 0.f, s3 = 0.f;
        #pragma unroll 4
        for (int k = 0; k < 64; k += 4) {
            s0 += midi_table[m * 64 + k + 0] * proj_w1[(192 + k + 0) * 256 + c];
            s1 += midi_table[m * 64 + k + 1] * proj_w1[(192 + k + 1) * 256 + c];
            s2 += midi_table[m * 64 + k + 2] * proj_w1[(192 + k + 2) * 256 + c];
            s3 += midi_table[m * 64 + k + 3] * proj_w1[(192 + k + 3) * 256 + c];
        }
        g_midiPh[m * 256 + c] = __float2half_rn((s0 + s1) + (s2 + s3));
    } else if (r < 260) {
        const int kd = r - 228;          // derived-K 0..31 (f0 part)
        float s0 = 0.f, s1 = 0.f, s2 = 0.f, s3 = 0.f;
        #pragma unroll 4
        for (int k = 0; k < 64; k += 4) {
            s0 += f0_w2[kd * 64 + k + 0] * proj_w1[(k + 0) * 256 + c];
            s1 += f0_w2[kd * 64 + k + 1] * proj_w1[(k + 1) * 256 + c];
            s2 += f0_w2[kd * 64 + k + 2] * proj_w1[(k + 2) * 256 + c];
            s3 += f0_w2[kd * 64 + k + 3] * proj_w1[(k + 3) * 256 + c];
        }
        g_W1H[((kd >> 4) * 256 + c) * 16 + slot16(kd & 15)] =
            __float2half_rn((s0 + s1) + (s2 + s3));
    } else if (r < 292) {
        const int j = r - 260;           // dur part -> derived-K 32..63
        const int kd = 32 + j;
        float s0 = 0.f, s1 = 0.f, s2 = 0.f, s3 = 0.f;
        #pragma unroll 4
        for (int k = 0; k < 64; k += 4) {
            s0 += dur_w2[j * 64 + k + 0] * proj_w1[(256 + k + 0) * 256 + c];
            s1 += dur_w2[j * 64 + k + 1] * proj_w1[(256 + k + 1) * 256 + c];
            s2 += dur_w2[j * 64 + k + 2] * proj_w1[(256 + k + 2) * 256 + c];
            s3 += dur_w2[j * 64 + k + 3] * proj_w1[(256 + k + 3) * 256 + c];
        }
        g_W1H[((kd >> 4) * 256 + c) * 16 + slot16(kd & 15)] =
            __float2half_rn((s0 + s1) + (s2 + s3));
    } else if (r < 293) {
        float s = proj_b1[c];
        #pragma unroll 4
        for (int k = 0; k < 64; k++) {
            s += f0_b2[k] * proj_w1[k * 256 + c];
            s += dur_b2[k] * proj_w1[(256 + k) * 256 + c];
        }
        g_bias[c] = s;
    } else {
        const int k = r - 293;           // 0..255: proj_w2 input-row k, col c
        g_W2H[((k >> 4) * 256 + c) * 16 + slot16(k & 15)] =
            __float2half_rn(proj_w2[k * 256 + c]);
    }
}

// ---------------- main fused fp16-mma kernel (2 CTAs/SM) ----------------
__global__ __launch_bounds__(256, 2)
void cond_enc_mma_kernel(
    const float* __restrict__ f0, const int* __restrict__ phone,
    const float* __restrict__ duration, const int* __restrict__ midi,
    const float* __restrict__ f0_w1, const float* __restrict__ f0_b1,
    const float* __restrict__ dur_w1, const float* __restrict__ dur_b1,
    const float* __restrict__ ln_g, const float* __restrict__ ln_b,
    const float* __restrict__ proj_b2,
    float* __restrict__ out, int npos) {
    extern __shared__ __align__(16) char smraw[];
    __half* sa1 = (__half*)smraw;                       // [64][72]
    __half* sA2 = sa1 + 64 * SA1H;                      // [64][264]
    float2* sPS = (float2*)(sA2 + 64 * SA2H);           // [64][9] partials
    float2* sMV = sPS + 64 * PS_STRIDE;                 // [64] (mu, rs)
    float* sbias = (float*)(sMV + 64);                  // [256]
    float* sg = sbias + 256;
    float* sb = sg + 256;
    float* sb2 = sb + 256;

    const int tid = threadIdx.x;
    const int lane = tid & 31;
    const int w = tid >> 5;          // warp w owns cols [w*32, w*32+32), all 64 rows
    const int n0w = w * 32;
    const int gid = lane >> 2;
    const int q = lane & 3;
    const int base = blockIdx.x * TM;

    // ldmatrix per-lane A offsets (b16, 16-k tiles)
    const int tA = lane >> 3;
    const int aRow = (lane & 7) + (tA & 1) * 8;
    const int aKof = (tA >> 1) * 8;       // halves

    const unsigned u_sa1 = smem_u32(sa1);
    const unsigned u_sA2 = smem_u32(sA2);

    const uint2* __restrict__ W1H = (const uint2*)g_W1H;
    const uint2* __restrict__ W2H = (const uint2*)g_W2H;
    int nIdx[4];
    #pragma unroll
    for (int nt = 0; nt < 4; nt++) nIdx[nt] = n0w + nt * 8 + gid;

    sbias[tid] = g_bias[tid];
    sg[tid] = ln_g[tid];
    sb[tid] = ln_b[tid];
    sb2[tid] = proj_b2[tid];

    // Phase 1: tiny MLPs -> sa1 (half2 stores)
    for (int idx = tid; idx < TM * 32; idx += 256) {
        const int t = idx >> 5;
        const int u = (idx & 31) * 2;
        int row = base + t; if (row >= npos) row = npos - 1;
        float v0, v1;
        if (u < 32) {
            const float fv = f0[row];
            v0 = fv * f0_w1[u] + f0_b1[u];
            v1 = fv * f0_w1[u + 1] + f0_b1[u + 1];
        } else {
            const float dv = duration[row];
            v0 = dv * dur_w1[u - 32] + dur_b1[u - 32];
            v1 = dv * dur_w1[u - 31] + dur_b1[u - 31];
        }
        *(__half2*)&sa1[t * SA1H + u] =
            __floats2half2_rn(fmaxf(v0, 0.f), fmaxf(v1, 0.f));
    }
    __syncthreads();   // (1) sa1 ready

    float acc[4][4][4];
    #pragma unroll
    for (int mt = 0; mt < 4; mt++)
        #pragma unroll
        for (int nt = 0; nt < 4; nt++)
            #pragma unroll
            for (int e = 0; e < 4; e++) acc[mt][nt][e] = 0.f;

    // Phase 2: GEMM1 (K=64 -> 4 fp16 k-tiles), B direct from L2
    {
        uint2 bq[2][4];
        #pragma unroll
        for (int nt = 0; nt < 4; nt++)
            bq[0][nt] = W1H[(0 * 256 + nIdx[nt]) * 4 + q];
        #pragma unroll
        for (int kt = 0; kt < 4; kt++) {
            const int cur = kt & 1, nxt = cur ^ 1;
            if (kt < 3) {
                #pragma unroll
                for (int nt = 0; nt < 4; nt++)
                    bq[nxt][nt] = W1H[((kt + 1) * 256 + nIdx[nt]) * 4 + q];
            }
            unsigned a[4][4];
            #pragma unroll
            for (int mt = 0; mt < 4; mt++)
                ldsm_x4(a[mt][0], a[mt][1], a[mt][2], a[mt][3],
                        u_sa1 + (unsigned)((mt * 16 + aRow) * SA1H +
                                           kt * 16 + aKof) * 2u);
            #pragma unroll
            for (int mt = 0; mt < 4; mt++)
                #pragma unroll
                for (int nt = 0; nt < 4; nt++)
                    mma_f16(acc[mt][nt], a[mt], (const unsigned*)&bq[cur][nt]);
        }
    }

    // Early prefetch of GEMM2's first B k-tile — hidden behind the whole LN phase.
    uint2 bq20[4];
    #pragma unroll
    for (int nt = 0; nt < 4; nt++)
        bq20[nt] = W2H[(0 * 256 + nIdx[nt]) * 4 + q];

    // Phase 3a: add bias + fp16 phone/midi table contributions in-register,
    // accumulate per-row partial sums for LayerNorm.
    {
        #pragma unroll
        for (int mt = 0; mt < 4; mt++) {
            const int r0 = mt * 16 + gid;
            const int r1 = r0 + 8;
            int g0 = base + r0; if (g0 >= npos) g0 = npos - 1;
            int g1 = base + r1; if (g1 >= npos) g1 = npos - 1;
            const __half* __restrict__ pp0 = &g_phonePh[phone[g0] * 256];
            const __half* __restrict__ mp0 = &g_midiPh[midi[g0] * 256];
            const __half* __restrict__ pp1 = &g_phonePh[phone[g1] * 256];
            const __half* __restrict__ mp1 = &g_midiPh[midi[g1] * 256];
            float s0 = 0.f, ss0 = 0.f, s1 = 0.f, ss1 = 0.f;
            #pragma unroll
            for (int nt = 0; nt < 4; nt++) {
                const int col = n0w + nt * 8 + q * 2;
                const float2 bb = *(const float2*)&sbias[col];
                const float2 a0 = __half22float2(*(const __half2*)&pp0[col]);
                const float2 b0 = __half22float2(*(const __half2*)&mp0[col]);
                const float2 a1 = __half22float2(*(const __half2*)&pp1[col]);
                const float2 b1 = __half22float2(*(const __half2*)&mp1[col]);
                float x0 = acc[mt][nt][0] + bb.x + a0.x + b0.x;
                float x1 = acc[mt][nt][1] + bb.y + a0.y + b0.y;
                float x2 = acc[mt][nt][2] + bb.x + a1.x + b1.x;
                float x3 = acc[mt][nt][3] + bb.y + a1.y + b1.y;
                acc[mt][nt][0] = x0; acc[mt][nt][1] = x1;
                acc[mt][nt][2] = x2; acc[mt][nt][3] = x3;
                s0 += x0 + x1; ss0 += x0 * x0 + x1 * x1;
                s1 += x2 + x3; ss1 += x2 * x2 + x3 * x3;
            }
            #pragma unroll
            for (int o = 1; o < 4; o <<= 1) {
                s0 += __shfl_xor_sync(0xffffffffu, s0, o);
                ss0 += __shfl_xor_sync(0xffffffffu, ss0, o);
                s1 += __shfl_xor_sync(0xffffffffu, s1, o);
                ss1 += __shfl_xor_sync(0xffffffffu, ss1, o);
            }
            if (q == 0) {
                sPS[r0 * PS_STRIDE + w] = make_float2(s0, ss0);
                sPS[r1 * PS_STRIDE + w] = make_float2(s1, ss1);
            }
        }
    }
    __syncthreads();   // (2) partials ready

    // Phase 3b: finalize mu/rs per row (threads 0..63)
    if (tid < 64) {
        float s = 0.f, ss = 0.f;
        #pragma unroll
        for (int j = 0; j < 8; j++) {
            const float2 ps = sPS[tid * PS_STRIDE + j];
            s += ps.x; ss += ps.y;
        }
        const float mu = s * (1.f / 256.f);
        float var = ss * (1.f / 256.f) - mu * mu;
        var = fmaxf(var, 0.f);
        sMV[tid] = make_float2(mu, rsqrtf(var + EPS));
    }
    __syncthreads();   // (3) mu/rs ready

    // Phase 3c: apply LN + ReLU in-register, write half A2 tile
    {
        #pragma unroll
        for (int mt = 0; mt < 4; mt++) {
            const int r0 = mt * 16 + gid;
            const int r1 = r0 + 8;
            const float2 mv0 = sMV[r0];
            const float2 mv1 = sMV[r1];
            #pragma unroll
            for (int nt = 0; nt < 4; nt++) {
                const int col = n0w + nt * 8 + q * 2;
                const float2 gg = *(const float2*)&sg[col];
                const float2 bb = *(const float2*)&sb[col];
                float x0 = fmaxf((acc[mt][nt][0] - mv0.x) * mv0.y * gg.x + bb.x, 0.f);
                float x1 = fmaxf((acc[mt][nt][1] - mv0.x) * mv0.y * gg.y + bb.y, 0.f);
                float x2 = fmaxf((acc[mt][nt][2] - mv1.x) * mv1.y * gg.x + bb.x, 0.f);
                float x3 = fmaxf((acc[mt][nt][3] - mv1.x) * mv1.y * gg.y + bb.y, 0.f);
                *(__half2*)&sA2[r0 * SA2H + col] = __floats2half2_rn(x0, x1);
                *(__half2*)&sA2[r1 * SA2H + col] = __floats2half2_rn(x2, x3);
            }
        }
    }
    __syncthreads();   // (4) A2 ready

    #pragma unroll
    for (int mt = 0; mt < 4; mt++)
        #pragma unroll
        for (int nt = 0; nt < 4; nt++)
            #pragma unroll
            for (int e = 0; e < 4; e++) acc[mt][nt][e] = 0.f;

    // Phase 4: GEMM2 (K=256 -> 16 fp16 k-tiles), barrier-free, B from L2
    {
        uint2 bq[2][4];
        #pragma unroll
        for (int nt = 0; nt < 4; nt++)
            bq[0][nt] = bq20[nt];
        #pragma unroll 4
        for (int kt = 0; kt < 16; kt++) {
            const int cur = kt & 1, nxt = cur ^ 1;
            if (kt < 15) {
                #pragma unroll
                for (int nt = 0; nt < 4; nt++)
                    bq[nxt][nt] = W2H[((kt + 1) * 256 + nIdx[nt]) * 4 + q];
            }
            unsigned a[4][4];
            #pragma unroll
            for (int mt = 0; mt < 4; mt++)
                ldsm_x4(a[mt][0], a[mt][1], a[mt][2], a[mt][3],
                        u_sA2 + (unsigned)((mt * 16 + aRow) * SA2H +
                                           kt * 16 + aKof) * 2u);
            #pragma unroll
            for (int mt = 0; mt < 4; mt++)
                #pragma unroll
                for (int nt = 0; nt < 4; nt++)
                    mma_f16(acc[mt][nt], a[mt], (const unsigned*)&bq[cur][nt]);
        }
    }

    // Phase 5: write output (+proj_b2)
    #pragma unroll
    for (int mt = 0; mt < 4; mt++) {
        const int row = mt * 16 + gid;
        #pragma unroll
        for (int nt = 0; nt < 4; nt++) {
            const int col = n0w + nt * 8 + q * 2;
            const float b2a = sb2[col];
            const float b2b = sb2[col + 1];
            if (base + row < npos)
                *(float2*)&out[(size_t)(base + row) * 256 + col] =
                    make_float2(acc[mt][nt][0] + b2a, acc[mt][nt][1] + b2b);
            if (base + row + 8 < npos)
                *(float2*)&out[(size_t)(base + row + 8) * 256 + col] =
                    make_float2(acc[mt][nt][2] + b2a, acc[mt][nt][3] + b2b);
        }
    }
}

extern "C" void kernel_launch(void* const* d_in, const int* in_sizes, int n_in,
                              void* d_out, int out_size) {
    const float* f0          = (const float*)d_in[0];
    const int*   phone       = (const int*)  d_in[1];
    const float* duration    = (const float*)d_in[2];
    const int*   midi        = (const int*)  d_in[3];
    const float* f0_w1       = (const float*)d_in[4];
    const float* f0_b1       = (const float*)d_in[5];
    const float* f0_w2       = (const float*)d_in[6];
    const float* f0_b2       = (const float*)d_in[7];
    const float* phone_table = (const float*)d_in[8];
    const float* midi_table  = (const float*)d_in[9];
    const float* dur_w1      = (const float*)d_in[10];
    const float* dur_b1      = (const float*)d_in[11];
    const float* dur_w2      = (const float*)d_in[12];
    const float* dur_b2      = (const float*)d_in[13];
    const float* proj_w1     = (const float*)d_in[14];
    const float* proj_b1     = (const float*)d_in[15];
    const float* ln_g        = (const float*)d_in[16];
    const float* ln_b        = (const float*)d_in[17];
    const float* proj_w2     = (const float*)d_in[18];
    const float* proj_b2     = (const float*)d_in[19];
    float* out = (float*)d_out;
    const int npos = in_sizes[0];

    precompute_kernel<<<549, 256>>>(f0_w2, f0_b2, phone_table, midi_table,
                                    dur_w2, dur_b2, proj_w1, proj_b1, proj_w2);

    const size_t smem_bytes =
        (size_t)(64 * SA1H + 64 * SA2H) * sizeof(__half) +
        (size_t)(64 * PS_STRIDE + 64) * sizeof(float2) +
        (size_t)(4 * 256) * sizeof(float) + 64;
    cudaFuncSetAttribute(cond_enc_mma_kernel,
                         cudaFuncAttributeMaxDynamicSharedMemorySize,
                         (int)smem_bytes);
    const int grid = (npos + TM - 1) / TM;
    cond_enc_mma_kernel<<<grid, 256, smem_bytes>>>(
        f0, phone, duration, midi, f0_w1, f0_b1, dur_w1, dur_b1,
        ln_g, ln_b, proj_b2, out, npos);
}